// round 16
// baseline (speedup 1.0000x reference)
#include <cuda_runtime.h>
#include <cuda_bf16.h>
#include <cstdint>

#define BB 4
#define LEN 512
#define LEN1 512
#define DIM_IN 512
#define DIM_H 512
#define DIM_M 256
#define DIM_V 512

#define LDK 20   // av smem k-stride (16 k + 4 pad) words
#define LDN 72   // av smem n-stride (64 n + 8 pad) words

#define L2E 1.4426950408889634f

// Scratch
__device__ __align__(16) float    g_kx[BB * LEN * DIM_M];   // [b][l][m]
__device__ __align__(16) float    g_qh[BB * LEN1 * DIM_M];  // [b][q][m]
__device__ __align__(16) float    g_sc[BB * LEN1 * LEN];    // [b][q][l]: exp(s) as tf32 bits
__device__ __align__(16) unsigned g_vt[BB * LEN * DIM_V];   // values as tf32 bits
__device__ __align__(16) float    g_part[BB * LEN1 * 16];   // per (row, l-tile): S_tile
__device__ int g_done[BB];                                  // per-batch completion counters

// score_av dynamic smem union:
//   score: kxs[128][34] (4352 w) + qhs[128][34] (4352 w) + w_s[256]  = 8960 w
//   av:    Es 4*64*20 (5120 w) + Vs 4*16*72 (4608 w) + sinv[64]      = 9792 w
#define SAV_WORDS 9792
#define SAV_SMEM  (SAV_WORDS * 4)

__device__ __forceinline__ float tanh_fast(float x) {
    float y;
    asm("tanh.approx.f32 %0, %1;" : "=f"(y) : "f"(x));
    return y;
}
__device__ __forceinline__ unsigned f2tf(float x) {
    unsigned u;
    asm("cvt.rna.tf32.f32 %0, %1;" : "=r"(u) : "f"(x));
    return u;
}
__device__ __forceinline__ void mma_tf32(float* d, const unsigned* a, const unsigned* b) {
    asm volatile(
        "mma.sync.aligned.m16n8k8.row.col.f32.tf32.tf32.f32 "
        "{%0,%1,%2,%3}, {%4,%5,%6,%7}, {%8,%9}, {%0,%1,%2,%3};"
        : "+f"(d[0]), "+f"(d[1]), "+f"(d[2]), "+f"(d[3])
        : "r"(a[0]), "r"(a[1]), "r"(a[2]), "r"(a[3]), "r"(b[0]), "r"(b[1]));
}
__device__ __forceinline__ void cp16(uint32_t smem_dst, const void* gmem_src) {
    asm volatile("cp.async.cg.shared.global [%0], [%1], 16;"
                 :: "r"(smem_dst), "l"(gmem_src));
}
#define CP_COMMIT() asm volatile("cp.async.commit_group;")
#define CP_WAIT2()  asm volatile("cp.async.wait_group 2;" ::: "memory")

// ---------------------------------------------------------------------------
// proj (NT, tf32 mma, 4-stage cp.async), per batch b. Block 64x64, 8 warps.
// z=0: keys[b]@Wx -> g_kx[b] ; z=1: query[b]@Wh + bh -> g_qh[b] ;
// z=2: rider blocks convert values[b] -> g_vt[b] (tf32 bits) AND block 0
//      resets the g_done counters for this call.
// ---------------------------------------------------------------------------
__global__ __launch_bounds__(256) void proj_tc(
    const float* __restrict__ keys, const float* __restrict__ query,
    const float* __restrict__ Wx, const float* __restrict__ Wh,
    const float* __restrict__ bh, const float* __restrict__ values, int b)
{
    int tid = threadIdx.x;

    if (blockIdx.z == 2) {
        int blk = blockIdx.y * 4 + blockIdx.x;        // 0..31
        if (blk == 0 && tid < BB) g_done[tid] = 0;    // reset counters (all writers write 0)
        size_t base = (size_t)b * LEN * DIM_V / 4;
        const float4* src = (const float4*)values + base;
        uint4* dst = (uint4*)g_vt + base;
        int t = blk * 256 + tid;                      // 0..8191
        #pragma unroll
        for (int i = 0; i < 8; i++) {
            int idx = t + i * 8192;
            float4 v = src[idx];
            uint4 u;
            u.x = f2tf(v.x); u.y = f2tf(v.y); u.z = f2tf(v.z); u.w = f2tf(v.w);
            dst[idx] = u;
        }
        return;
    }

    const float* A; const float* W; float* C; const float* bias;
    if (blockIdx.z == 0) {
        A = keys  + (size_t)b * LEN * DIM_IN;  W = Wx;
        C = g_kx  + (size_t)b * LEN * DIM_M;   bias = nullptr;
    } else {
        A = query + (size_t)b * LEN1 * DIM_H;  W = Wh;
        C = g_qh  + (size_t)b * LEN1 * DIM_M;  bias = bh;
    }

    __shared__ __align__(16) float As[4][64 * LDK];
    __shared__ __align__(16) float Ws[4][64 * LDK];

    int lane = tid & 31;
    int wid  = tid >> 5;
    int warp_m = (wid & 1) * 32;
    int warp_n = (wid >> 1) * 16;
    int gid = lane >> 2;
    int tig = lane & 3;

    int rb = blockIdx.y * 64;
    int nb = blockIdx.x * 64;

    int crow = tid >> 2;
    int cku  = (tid & 3) * 4;
    const float* Agp = A + (size_t)(rb + crow) * 512 + cku;
    const float* Wgp = W + (size_t)(nb + crow) * 512 + cku;
    uint32_t sA = (uint32_t)__cvta_generic_to_shared(&As[0][0]) + (crow * LDK + cku) * 4;
    uint32_t sW = (uint32_t)__cvta_generic_to_shared(&Ws[0][0]) + (crow * LDK + cku) * 4;
    const uint32_t stageB = 64 * LDK * 4;

    float acc[2][2][4] = {};

    #pragma unroll
    for (int s = 0; s < 3; s++) {
        cp16(sA + s * stageB, Agp + s * 16);
        cp16(sW + s * stageB, Wgp + s * 16);
        CP_COMMIT();
    }

    for (int i = 0; i < 32; i++) {
        CP_WAIT2();
        __syncthreads();
        int ls = i + 3;
        if (ls < 32) {
            uint32_t off = (uint32_t)(ls & 3) * stageB;
            cp16(sA + off, Agp + ls * 16);
            cp16(sW + off, Wgp + ls * 16);
        }
        CP_COMMIT();

        const float* Ab = &As[i & 3][0];
        const float* Wb = &Ws[i & 3][0];
        #pragma unroll
        for (int ks = 0; ks < 16; ks += 8) {
            unsigned af[2][4], bf[2][2];
            #pragma unroll
            for (int mm = 0; mm < 2; mm++) {
                const float* p = &Ab[(warp_m + mm * 16 + gid) * LDK + ks + tig];
                af[mm][0] = f2tf(p[0]);
                af[mm][1] = f2tf(p[8 * LDK]);
                af[mm][2] = f2tf(p[4]);
                af[mm][3] = f2tf(p[8 * LDK + 4]);
            }
            #pragma unroll
            for (int nn = 0; nn < 2; nn++) {
                const float* p = &Wb[(warp_n + nn * 8 + gid) * LDK + ks + tig];
                bf[nn][0] = f2tf(p[0]);
                bf[nn][1] = f2tf(p[4]);
            }
            #pragma unroll
            for (int mm = 0; mm < 2; mm++)
                #pragma unroll
                for (int nn = 0; nn < 2; nn++)
                    mma_tf32(acc[mm][nn], af[mm], bf[nn]);
        }
    }

    #pragma unroll
    for (int mm = 0; mm < 2; mm++) {
        int r0 = rb + warp_m + mm * 16 + gid;
        #pragma unroll
        for (int nn = 0; nn < 2; nn++) {
            int c = nb + warp_n + nn * 8 + 2 * tig;
            float2 v0 = make_float2(acc[mm][nn][0], acc[mm][nn][1]);
            float2 v1 = make_float2(acc[mm][nn][2], acc[mm][nn][3]);
            if (bias) {
                float2 bb = *(const float2*)&bias[c];
                v0.x += bb.x; v0.y += bb.y;
                v1.x += bb.x; v1.y += bb.y;
            }
            *(float2*)&C[(size_t)r0 * DIM_M + c]       = v0;
            *(float2*)&C[(size_t)(r0 + 8) * DIM_M + c] = v1;
        }
    }
}

// ---------------------------------------------------------------------------
// score_av: ONE kernel, grid (16,16,4), z = batch (z-outermost linear ids ->
// batch-0 CTAs scheduled first).
// Phase 1 (all 1024 CTAs): score tile -> e = exp2(s*L2E) as tf32 bits +
//   per-(row, l-tile) sums in g_part; threadfence + per-batch atomic count.
// Phase 2 (last 64 finishers per batch): morph into av CTAs for that batch:
//   prefetch V (ready since proj), acquire-spin for g_done[b]==256, then
//   64x64 tf32-mma av tile with epilogue 1/S normalization -> out.
// 192 CTAs/batch exit immediately -> slots always free -> no deadlock.
// ---------------------------------------------------------------------------
__global__ __launch_bounds__(256) void score_av(
    const float* __restrict__ w, float* __restrict__ out)
{
    extern __shared__ float sm[];
    float* kxs = sm;                 // [128][34]
    float* qhs = sm + 4352;          // [128][34]
    float* w_s = sm + 8704;          // [256]
    __shared__ int s_ret;

    int tid = threadIdx.x;
    int b   = blockIdx.z;
    int tx = tid & 15, ty = tid >> 4;
    int lb = blockIdx.x * 32;
    int qb = blockIdx.y * 32;

    w_s[tid] = w[tid];

    const float* kxp = g_kx + (size_t)(b * LEN  + lb) * DIM_M;
    const float* qhp = g_qh + (size_t)(b * LEN1 + qb) * DIM_M;

    float acc00 = 0.f, acc01 = 0.f, acc10 = 0.f, acc11 = 0.f;

    int mloc  = tid & 127;
    int lhalf = tid >> 7;

    for (int h = 0; h < 2; h++) {
        __syncthreads();
        int mg = h * 128 + mloc;
        #pragma unroll
        for (int i = 0; i < 16; i++) {
            int row = lhalf * 16 + i;
            kxs[mloc * 34 + row] = kxp[row * DIM_M + mg];
            qhs[mloc * 34 + row] = qhp[row * DIM_M + mg];
        }
        __syncthreads();

        #pragma unroll 8
        for (int mm = 0; mm < 128; mm++) {
            float  wm = w_s[h * 128 + mm];
            float2 qa = *(const float2*)&qhs[mm * 34 + ty * 2];
            float2 kb = *(const float2*)&kxs[mm * 34 + tx * 2];
            acc00 += wm * tanh_fast(qa.x + kb.x);
            acc01 += wm * tanh_fast(qa.x + kb.y);
            acc10 += wm * tanh_fast(qa.y + kb.x);
            acc11 += wm * tanh_fast(qa.y + kb.y);
        }
    }

    float e00 = exp2f(acc00 * L2E);
    float e01 = exp2f(acc01 * L2E);
    float e10 = exp2f(acc10 * L2E);
    float e11 = exp2f(acc11 * L2E);

    float S0 = e00 + e01;
    float S1 = e10 + e11;
    #pragma unroll
    for (int s = 1; s < 16; s <<= 1) {
        S0 += __shfl_xor_sync(0xFFFFFFFFu, S0, s);
        S1 += __shfl_xor_sync(0xFFFFFFFFu, S1, s);
    }

    float* o = g_sc + (size_t)(b * LEN1 + qb + ty * 2) * LEN + lb + tx * 2;
    o[0]       = __uint_as_float(f2tf(e00));
    o[1]       = __uint_as_float(f2tf(e01));
    o[LEN]     = __uint_as_float(f2tf(e10));
    o[LEN + 1] = __uint_as_float(f2tf(e11));

    if (tx == 0) {
        int q0 = qb + ty * 2;
        float* pp = g_part + (size_t)(b * LEN1 + q0) * 16 + blockIdx.x;
        pp[0]  = S0;
        pp[16] = S1;
    }

    // ---- completion count; last 64 finishers become av workers ----
    __threadfence();
    __syncthreads();
    if (tid == 0) s_ret = atomicAdd(&g_done[b], 1);
    __syncthreads();
    int ret = s_ret;
    if (ret < 192) return;

    int tile = ret - 192;            // 0..63
    int arb = (tile >> 3) * 64;      // q base
    int nbv = (tile & 7) * 64;       // v base

    // ---- av phase (smem reused; score smem reads finished above) ----
    __syncthreads();                 // all threads past score smem use
    unsigned* Es   = (unsigned*)sm;          // 4 stages * 64*LDK = 5120 w
    unsigned* Vs   = (unsigned*)sm + 5120;   // 4 stages * 16*LDN = 4608 w
    float*    sinv = sm + 9728;              // [64]

    const unsigned* E = (const unsigned*)g_sc + (size_t)b * LEN1 * LEN;
    const unsigned* V = g_vt + (size_t)b * LEN * DIM_V;
    float*          C = out  + (size_t)b * LEN1 * DIM_V;

    int lane = tid & 31;
    int wid  = tid >> 5;
    int warp_m = (wid & 1) * 32;
    int warp_n = (wid >> 1) * 16;
    int gid = lane >> 2;
    int tig = lane & 3;

    int erow = tid >> 2;
    int eku  = (tid & 3) * 4;
    int vrow = tid >> 4;
    int vu   = (tid & 15) * 4;
    const unsigned* Egp = E + (size_t)(arb + erow) * LEN + eku;
    const unsigned* Vgp = V + (size_t)vrow * DIM_V + nbv + vu;
    uint32_t sE = (uint32_t)__cvta_generic_to_shared(Es) + (erow * LDK + eku) * 4;
    uint32_t sV = (uint32_t)__cvta_generic_to_shared(Vs) + (vrow * LDN + vu) * 4;
    const uint32_t stageE = 64 * LDK * 4;
    const uint32_t stageV = 16 * LDN * 4;

    // V prefetch (g_vt ready since proj): groups 0..2
    #pragma unroll
    for (int s = 0; s < 3; s++) {
        cp16(sV + s * stageV, Vgp + (size_t)s * 16 * DIM_V);
        CP_COMMIT();
    }

    // Wait for ALL score CTAs of this batch (acquire).
    if (tid == 0) {
        int v;
        do {
            asm volatile("ld.acquire.gpu.b32 %0, [%1];"
                         : "=r"(v) : "l"(&g_done[b]) : "memory");
        } while (v < 256);
    }
    __syncthreads();

    // E stages: groups 3..5 (stage i ready iff group 3+i done -> mainloop's
    // wait_group 2 algebra unchanged).
    #pragma unroll
    for (int s = 0; s < 3; s++) {
        cp16(sE + s * stageE, Egp + s * 16);
        CP_COMMIT();
    }

    float acc[2][2][4] = {};

    if (tid < 64) {
        const float4* pp = (const float4*)&g_part[(size_t)(b * LEN1 + arb + tid) * 16];
        float4 p0 = pp[0], p1 = pp[1], p2 = pp[2], p3 = pp[3];
        float S = ((p0.x + p0.y) + (p0.z + p0.w))
                + ((p1.x + p1.y) + (p1.z + p1.w))
                + ((p2.x + p2.y) + (p2.z + p2.w))
                + ((p3.x + p3.y) + (p3.z + p3.w));
        sinv[tid] = 1.0f / S;
    }
    __syncthreads();

    for (int i = 0; i < 32; i++) {
        CP_WAIT2();
        __syncthreads();
        int ls = i + 3;
        if (ls < 32) {
            uint32_t offE = (uint32_t)(ls & 3) * stageE;
            uint32_t offV = (uint32_t)(ls & 3) * stageV;
            cp16(sE + offE, Egp + ls * 16);
            cp16(sV + offV, Vgp + (size_t)ls * 16 * DIM_V);
        }
        CP_COMMIT();

        const unsigned* Eb = &Es[(i & 3) * 64 * LDK];
        const unsigned* Vb = &Vs[(i & 3) * 16 * LDN];
        #pragma unroll
        for (int ks = 0; ks < 16; ks += 8) {
            unsigned af[2][4], bf[2][2];
            #pragma unroll
            for (int mm = 0; mm < 2; mm++) {
                const unsigned* p = &Eb[(warp_m + mm * 16 + gid) * LDK + ks + tig];
                af[mm][0] = p[0];
                af[mm][1] = p[8 * LDK];
                af[mm][2] = p[4];
                af[mm][3] = p[8 * LDK + 4];
            }
            #pragma unroll
            for (int nn = 0; nn < 2; nn++) {
                const unsigned* p = &Vb[(ks + tig) * LDN + warp_n + nn * 8 + gid];
                bf[nn][0] = p[0];
                bf[nn][1] = p[4 * LDN];
            }
            #pragma unroll
            for (int mm = 0; mm < 2; mm++)
                #pragma unroll
                for (int nn = 0; nn < 2; nn++)
                    mma_tf32(acc[mm][nn], af[mm], bf[nn]);
        }
    }

    #pragma unroll
    for (int mm = 0; mm < 2; mm++) {
        int a  = warp_m + mm * 16 + gid;
        int r0 = arb + a;
        float sa = sinv[a];
        float sb = sinv[a + 8];
        #pragma unroll
        for (int nn = 0; nn < 2; nn++) {
            int c = nbv + warp_n + nn * 8 + 2 * tig;
            *(float2*)&C[(size_t)r0 * DIM_V + c] =
                make_float2(acc[mm][nn][0] * sa, acc[mm][nn][1] * sa);
            *(float2*)&C[(size_t)(r0 + 8) * DIM_V + c] =
                make_float2(acc[mm][nn][2] * sb, acc[mm][nn][3] * sb);
        }
    }
}

// ---------------------------------------------------------------------------
// Launch: 4 streams for proj (parallel), then ONE merged score_av kernel on
// st[0] after all projs (events). In-kernel atomics handle score->av
// staggering per batch.
// ---------------------------------------------------------------------------
extern "C" void kernel_launch(void* const* d_in, const int* in_sizes, int n_in,
                              void* d_out, int out_size)
{
    const float* query  = (const float*)d_in[0];
    const float* keys   = (const float*)d_in[1];
    const float* values = (const float*)d_in[2];
    const float* Wx     = (const float*)d_in[3];
    const float* Wh     = (const float*)d_in[4];
    const float* bh     = (const float*)d_in[5];
    const float* w      = (const float*)d_in[6];
    float* out = (float*)d_out;

    cudaStream_t st[BB];
    cudaEvent_t  evFork, evProj[BB], evJoin;
    for (int b = 0; b < BB; b++)
        cudaStreamCreateWithFlags(&st[b], cudaStreamNonBlocking);
    cudaEventCreateWithFlags(&evFork, cudaEventDisableTiming);
    for (int b = 0; b < BB; b++)
        cudaEventCreateWithFlags(&evProj[b], cudaEventDisableTiming);
    cudaEventCreateWithFlags(&evJoin, cudaEventDisableTiming);

    cudaEventRecord(evFork, 0);

    for (int b = 0; b < BB; b++) {
        cudaStreamWaitEvent(st[b], evFork, 0);
        proj_tc<<<dim3(DIM_M / 64, LEN / 64, 3), 256, 0, st[b]>>>(
            keys, query, Wx, Wh, bh, values, b);
        cudaEventRecord(evProj[b], st[b]);
    }

    for (int b = 1; b < BB; b++)
        cudaStreamWaitEvent(st[0], evProj[b], 0);

    score_av<<<dim3(LEN / 32, LEN1 / 32, BB), 256, SAV_SMEM, st[0]>>>(w, out);

    cudaEventRecord(evJoin, st[0]);
    cudaStreamWaitEvent((cudaStream_t)0, evJoin, 0);

    cudaEventDestroy(evFork);
    cudaEventDestroy(evJoin);
    for (int b = 0; b < BB; b++) {
        cudaEventDestroy(evProj[b]);
        cudaStreamDestroy(st[b]);
    }
}

// round 17
// speedup vs baseline: 1.2858x; 1.2858x over previous
#include <cuda_runtime.h>
#include <cuda_bf16.h>
#include <cstdint>

#define BB 4
#define LEN 512
#define LEN1 512
#define DIM_IN 512
#define DIM_H 512
#define DIM_M 256
#define DIM_V 512

#define LDK 20   // smem k-stride (16 k + 4 pad) words
#define LDN 72   // smem n-stride (64 n + 8 pad) words

// Scratch
__device__ __align__(16) float g_kx[BB * LEN * DIM_M];   // [b][l][m]
__device__ __align__(16) float g_qh[BB * LEN1 * DIM_M];  // [b][q][m]
__device__ __align__(16) float g_sc[BB * LEN1 * LEN];    // [b][q][l]; softmax leaves tf32 bits

__device__ __forceinline__ float tanh_fast(float x) {
    float y;
    asm("tanh.approx.f32 %0, %1;" : "=f"(y) : "f"(x));
    return y;
}
__device__ __forceinline__ unsigned f2tf(float x) {
    unsigned u;
    asm("cvt.rna.tf32.f32 %0, %1;" : "=r"(u) : "f"(x));
    return u;
}
__device__ __forceinline__ void mma_tf32(float* d, const unsigned* a, const unsigned* b) {
    asm volatile(
        "mma.sync.aligned.m16n8k8.row.col.f32.tf32.tf32.f32 "
        "{%0,%1,%2,%3}, {%4,%5,%6,%7}, {%8,%9}, {%0,%1,%2,%3};"
        : "+f"(d[0]), "+f"(d[1]), "+f"(d[2]), "+f"(d[3])
        : "r"(a[0]), "r"(a[1]), "r"(a[2]), "r"(a[3]), "r"(b[0]), "r"(b[1]));
}
__device__ __forceinline__ void cp16(uint32_t smem_dst, const void* gmem_src) {
    asm volatile("cp.async.cg.shared.global [%0], [%1], 16;"
                 :: "r"(smem_dst), "l"(gmem_src));
}
#define CP_COMMIT() asm volatile("cp.async.commit_group;")
#define CP_WAIT2()  asm volatile("cp.async.wait_group 2;" ::: "memory")

// ---------------------------------------------------------------------------
// proj (NT, tf32 mma, 4-stage cp.async), per batch b. Block 64x64, 8 warps.
// z=0: keys[b]@Wx -> g_kx[b] ; z=1: query[b]@Wh + bh -> g_qh[b].
// Grid = (4, 8, 2) per batch.  (Measured-best R6 kernel, unchanged.)
// ---------------------------------------------------------------------------
__global__ __launch_bounds__(256) void proj_tc(
    const float* __restrict__ keys, const float* __restrict__ query,
    const float* __restrict__ Wx, const float* __restrict__ Wh,
    const float* __restrict__ bh, int b)
{
    const float* A; const float* W; float* C; const float* bias;
    if (blockIdx.z == 0) {
        A = keys  + (size_t)b * LEN * DIM_IN;  W = Wx;
        C = g_kx  + (size_t)b * LEN * DIM_M;   bias = nullptr;
    } else {
        A = query + (size_t)b * LEN1 * DIM_H;  W = Wh;
        C = g_qh  + (size_t)b * LEN1 * DIM_M;  bias = bh;
    }

    __shared__ __align__(16) float As[4][64 * LDK];
    __shared__ __align__(16) float Ws[4][64 * LDK];

    int tid  = threadIdx.x;
    int lane = tid & 31;
    int wid  = tid >> 5;
    int warp_m = (wid & 1) * 32;
    int warp_n = (wid >> 1) * 16;
    int gid = lane >> 2;
    int tig = lane & 3;

    int rb = blockIdx.y * 64;
    int nb = blockIdx.x * 64;

    int crow = tid >> 2;
    int cku  = (tid & 3) * 4;
    const float* Agp = A + (size_t)(rb + crow) * 512 + cku;
    const float* Wgp = W + (size_t)(nb + crow) * 512 + cku;
    uint32_t sA = (uint32_t)__cvta_generic_to_shared(&As[0][0]) + (crow * LDK + cku) * 4;
    uint32_t sW = (uint32_t)__cvta_generic_to_shared(&Ws[0][0]) + (crow * LDK + cku) * 4;
    const uint32_t stageB = 64 * LDK * 4;

    float acc[2][2][4] = {};

    #pragma unroll
    for (int s = 0; s < 3; s++) {
        cp16(sA + s * stageB, Agp + s * 16);
        cp16(sW + s * stageB, Wgp + s * 16);
        CP_COMMIT();
    }

    for (int i = 0; i < 32; i++) {
        CP_WAIT2();
        __syncthreads();
        int ls = i + 3;
        if (ls < 32) {
            uint32_t off = (uint32_t)(ls & 3) * stageB;
            cp16(sA + off, Agp + ls * 16);
            cp16(sW + off, Wgp + ls * 16);
        }
        CP_COMMIT();

        const float* Ab = &As[i & 3][0];
        const float* Wb = &Ws[i & 3][0];
        #pragma unroll
        for (int ks = 0; ks < 16; ks += 8) {
            unsigned af[2][4], bf[2][2];
            #pragma unroll
            for (int mm = 0; mm < 2; mm++) {
                const float* p = &Ab[(warp_m + mm * 16 + gid) * LDK + ks + tig];
                af[mm][0] = f2tf(p[0]);
                af[mm][1] = f2tf(p[8 * LDK]);
                af[mm][2] = f2tf(p[4]);
                af[mm][3] = f2tf(p[8 * LDK + 4]);
            }
            #pragma unroll
            for (int nn = 0; nn < 2; nn++) {
                const float* p = &Wb[(warp_n + nn * 8 + gid) * LDK + ks + tig];
                bf[nn][0] = f2tf(p[0]);
                bf[nn][1] = f2tf(p[4]);
            }
            #pragma unroll
            for (int mm = 0; mm < 2; mm++)
                #pragma unroll
                for (int nn = 0; nn < 2; nn++)
                    mma_tf32(acc[mm][nn], af[mm], bf[nn]);
        }
    }

    #pragma unroll
    for (int mm = 0; mm < 2; mm++) {
        int r0 = rb + warp_m + mm * 16 + gid;
        #pragma unroll
        for (int nn = 0; nn < 2; nn++) {
            int c = nb + warp_n + nn * 8 + 2 * tig;
            float2 v0 = make_float2(acc[mm][nn][0], acc[mm][nn][1]);
            float2 v1 = make_float2(acc[mm][nn][2], acc[mm][nn][3]);
            if (bias) {
                float2 bb = *(const float2*)&bias[c];
                v0.x += bb.x; v0.y += bb.y;
                v1.x += bb.x; v1.y += bb.y;
            }
            *(float2*)&C[(size_t)r0 * DIM_M + c]       = v0;
            *(float2*)&C[(size_t)(r0 + 8) * DIM_M + c] = v1;
        }
    }
}

// ---------------------------------------------------------------------------
// Scores (measured-best R6 kernel, unchanged):
// sc[b][q][l] = sum_m w[m] * tanh(kx[b][l][m] + qh[b][q][m])
// 32(l) x 32(q) tile per block, 256 threads, 2x2 microtile.
// ---------------------------------------------------------------------------
__global__ __launch_bounds__(256) void score_kernel(const float* __restrict__ w, int b)
{
    __shared__ float kxs[128][34];
    __shared__ float qhs[128][34];
    __shared__ float w_s[DIM_M];

    int tid = threadIdx.x;
    int tx = tid & 15, ty = tid >> 4;
    int lb = blockIdx.x * 32;
    int qb = blockIdx.y * 32;

    if (tid < DIM_M) w_s[tid] = w[tid];

    const float* kxp = g_kx + (size_t)(b * LEN  + lb) * DIM_M;
    const float* qhp = g_qh + (size_t)(b * LEN1 + qb) * DIM_M;

    float acc00 = 0.f, acc01 = 0.f, acc10 = 0.f, acc11 = 0.f;

    int mloc  = tid & 127;
    int lhalf = tid >> 7;

    for (int h = 0; h < 2; h++) {
        __syncthreads();
        int mg = h * 128 + mloc;
        #pragma unroll
        for (int i = 0; i < 16; i++) {
            int row = lhalf * 16 + i;
            kxs[mloc][row] = kxp[row * DIM_M + mg];
            qhs[mloc][row] = qhp[row * DIM_M + mg];
        }
        __syncthreads();

        #pragma unroll 8
        for (int mm = 0; mm < 128; mm++) {
            float  wm = w_s[h * 128 + mm];
            float2 qa = *(const float2*)&qhs[mm][ty * 2];
            float2 kb = *(const float2*)&kxs[mm][tx * 2];
            acc00 += wm * tanh_fast(qa.x + kb.x);
            acc01 += wm * tanh_fast(qa.x + kb.y);
            acc10 += wm * tanh_fast(qa.y + kb.x);
            acc11 += wm * tanh_fast(qa.y + kb.y);
        }
    }

    float* o = g_sc + (size_t)(b * LEN1 + qb + ty * 2) * LEN + lb + tx * 2;
    o[0]       = acc00; o[1]       = acc01;
    o[LEN]     = acc10; o[LEN + 1] = acc11;
}

// ---------------------------------------------------------------------------
// Softmax over last dim (512) of g_sc[b], one warp per row; output stored as
// tf32 bits. (Measured-best R6 kernel, unchanged.) Grid = 64 per batch.
// ---------------------------------------------------------------------------
__global__ __launch_bounds__(256) void softmax_kernel(int b)
{
    int row  = b * LEN1 + blockIdx.x * 8 + (threadIdx.x >> 5);
    int lane = threadIdx.x & 31;
    float* p = g_sc + (size_t)row * LEN;

    float4 v[4];
    float mx = -1e30f;
    #pragma unroll
    for (int j = 0; j < 4; j++) {
        v[j] = *(float4*)&p[(lane + j * 32) * 4];
        mx = fmaxf(mx, fmaxf(fmaxf(v[j].x, v[j].y), fmaxf(v[j].z, v[j].w)));
    }
    #pragma unroll
    for (int s = 16; s > 0; s >>= 1)
        mx = fmaxf(mx, __shfl_xor_sync(0xFFFFFFFFu, mx, s));

    float sum = 0.f;
    #pragma unroll
    for (int j = 0; j < 4; j++) {
        v[j].x = __expf(v[j].x - mx); v[j].y = __expf(v[j].y - mx);
        v[j].z = __expf(v[j].z - mx); v[j].w = __expf(v[j].w - mx);
        sum += (v[j].x + v[j].y) + (v[j].z + v[j].w);
    }
    #pragma unroll
    for (int s = 16; s > 0; s >>= 1)
        sum += __shfl_xor_sync(0xFFFFFFFFu, sum, s);
    float inv = 1.0f / sum;

    #pragma unroll
    for (int j = 0; j < 4; j++) {
        float4 o;
        o.x = __uint_as_float(f2tf(v[j].x * inv));
        o.y = __uint_as_float(f2tf(v[j].y * inv));
        o.z = __uint_as_float(f2tf(v[j].z * inv));
        o.w = __uint_as_float(f2tf(v[j].w * inv));
        *(float4*)&p[(lane + j * 32) * 4] = o;
    }
}

// ---------------------------------------------------------------------------
// av (NN, tf32 mma, 4-stage cp.async), per batch b. Block 64x64, 8 warps.
// E comes in as tf32 bits (softmax output). V is RAW fp32 from the harness
// buffer; cvt.rna.tf32 applied in the B-fragment path (4 cvt/ks-step) —
// this replaces the former vt_cvt kernel, removing ~4.4us from every
// chain's critical path. Grid = (8, 8) per batch.
// ---------------------------------------------------------------------------
__global__ __launch_bounds__(256) void av_tc(
    const float* __restrict__ values, float* __restrict__ out, int b)
{
    const unsigned* E = (const unsigned*)g_sc + (size_t)b * LEN1 * LEN;
    const float*    V = values + (size_t)b * LEN * DIM_V;
    float*          C = out    + (size_t)b * LEN1 * DIM_V;

    __shared__ __align__(16) unsigned Es[4][64 * LDK];
    __shared__ __align__(16) float    Vs[4][16 * LDN];

    int tid  = threadIdx.x;
    int lane = tid & 31;
    int wid  = tid >> 5;
    int warp_m = (wid & 1) * 32;
    int warp_n = (wid >> 1) * 16;
    int gid = lane >> 2;
    int tig = lane & 3;

    int rb = blockIdx.y * 64;   // q
    int nb = blockIdx.x * 64;   // v

    int erow = tid >> 2;
    int eku  = (tid & 3) * 4;
    int vrow = tid >> 4;
    int vu   = (tid & 15) * 4;
    const unsigned* Egp = E + (size_t)(rb + erow) * LEN + eku;
    const float*    Vgp = V + (size_t)vrow * DIM_V + nb + vu;
    uint32_t sE = (uint32_t)__cvta_generic_to_shared(&Es[0][0]) + (erow * LDK + eku) * 4;
    uint32_t sV = (uint32_t)__cvta_generic_to_shared(&Vs[0][0]) + (vrow * LDN + vu) * 4;
    const uint32_t stageE = 64 * LDK * 4;
    const uint32_t stageV = 16 * LDN * 4;

    float acc[2][2][4] = {};

    #pragma unroll
    for (int s = 0; s < 3; s++) {
        cp16(sE + s * stageE, Egp + s * 16);
        cp16(sV + s * stageV, Vgp + (size_t)s * 16 * DIM_V);
        CP_COMMIT();
    }

    for (int i = 0; i < 32; i++) {
        CP_WAIT2();
        __syncthreads();
        int ls = i + 3;
        if (ls < 32) {
            uint32_t offE = (uint32_t)(ls & 3) * stageE;
            uint32_t offV = (uint32_t)(ls & 3) * stageV;
            cp16(sE + offE, Egp + ls * 16);
            cp16(sV + offV, Vgp + (size_t)ls * 16 * DIM_V);
        }
        CP_COMMIT();

        const unsigned* Eb = &Es[i & 3][0];
        const float*    Vb = &Vs[i & 3][0];
        #pragma unroll
        for (int ks = 0; ks < 16; ks += 8) {
            unsigned af[2][4], bf[2][2];
            #pragma unroll
            for (int mm = 0; mm < 2; mm++) {
                const unsigned* p = &Eb[(warp_m + mm * 16 + gid) * LDK + ks + tig];
                af[mm][0] = p[0];
                af[mm][1] = p[8 * LDK];
                af[mm][2] = p[4];
                af[mm][3] = p[8 * LDK + 4];
            }
            #pragma unroll
            for (int nn = 0; nn < 2; nn++) {
                const float* p = &Vb[(ks + tig) * LDN + warp_n + nn * 8 + gid];
                bf[nn][0] = f2tf(p[0]);
                bf[nn][1] = f2tf(p[4 * LDN]);
            }
            #pragma unroll
            for (int mm = 0; mm < 2; mm++)
                #pragma unroll
                for (int nn = 0; nn < 2; nn++)
                    mma_tf32(acc[mm][nn], af[mm], bf[nn]);
        }
    }

    #pragma unroll
    for (int mm = 0; mm < 2; mm++) {
        int r0 = rb + warp_m + mm * 16 + gid;
        #pragma unroll
        for (int nn = 0; nn < 2; nn++) {
            int c = nb + warp_n + nn * 8 + 2 * tig;
            *(float2*)&C[(size_t)r0 * DIM_V + c] =
                make_float2(acc[mm][nn][0], acc[mm][nn][1]);
            *(float2*)&C[(size_t)(r0 + 8) * DIM_V + c] =
                make_float2(acc[mm][nn][2], acc[mm][nn][3]);
        }
    }
}

// ---------------------------------------------------------------------------
// Launch: EXACT measured-best R6 topology (4 streams, fork-join, no
// cross-chain edges), minus the vt_cvt kernel.
// Chain b: proj -> score -> softmax -> av(in-loop V cvt).
// ---------------------------------------------------------------------------
extern "C" void kernel_launch(void* const* d_in, const int* in_sizes, int n_in,
                              void* d_out, int out_size)
{
    const float* query  = (const float*)d_in[0];
    const float* keys   = (const float*)d_in[1];
    const float* values = (const float*)d_in[2];
    const float* Wx     = (const float*)d_in[3];
    const float* Wh     = (const float*)d_in[4];
    const float* bh     = (const float*)d_in[5];
    const float* w      = (const float*)d_in[6];
    float* out = (float*)d_out;

    cudaStream_t st[BB];
    cudaEvent_t  evFork, evJoin[BB];
    for (int b = 0; b < BB; b++)
        cudaStreamCreateWithFlags(&st[b], cudaStreamNonBlocking);
    cudaEventCreateWithFlags(&evFork, cudaEventDisableTiming);
    for (int b = 0; b < BB; b++)
        cudaEventCreateWithFlags(&evJoin[b], cudaEventDisableTiming);

    cudaEventRecord(evFork, 0);

    for (int b = 0; b < BB; b++) {
        cudaStreamWaitEvent(st[b], evFork, 0);
        proj_tc<<<dim3(DIM_M / 64, LEN / 64, 2), 256, 0, st[b]>>>(
            keys, query, Wx, Wh, bh, b);
        score_kernel<<<dim3(LEN / 32, LEN1 / 32), 256, 0, st[b]>>>(w, b);
        softmax_kernel<<<LEN1 / 8, 256, 0, st[b]>>>(b);
        av_tc<<<dim3(DIM_V / 64, LEN1 / 64), 256, 0, st[b]>>>(values, out, b);
        cudaEventRecord(evJoin[b], st[b]);
    }

    for (int b = 0; b < BB; b++)
        cudaStreamWaitEvent((cudaStream_t)0, evJoin[b], 0);

    cudaEventDestroy(evFork);
    for (int b = 0; b < BB; b++) {
        cudaEventDestroy(evJoin[b]);
        cudaStreamDestroy(st[b]);
    }
}